// round 6
// baseline (speedup 1.0000x reference)
#include <cuda_runtime.h>

#define V      10
#define L      45          // V*(V-1)/2
#define NCOEF  14
#define RPB    128         // rows per block == threads per block
#define TPB    128
#define MTILE  32          // rows staged per M phase (4 phases)
#define XPAD   11          // padded row stride for s_x

__device__ __forceinline__ float warp_sum(float v) {
#pragma unroll
    for (int o = 16; o > 0; o >>= 1) v += __shfl_down_sync(0xffffffffu, v, o);
    return v;
}

__global__ __launch_bounds__(TPB, 6)
void decor_kernel(const float* __restrict__ x,
                  const float* __restrict__ log_d,
                  const float* __restrict__ params,
                  float* __restrict__ out_all,
                  int n_rows)
{
    const int t = threadIdx.x;
    const int nblocks_main = (int)gridDim.x - 1;

    // ---------------- penalty block (last block): params-only ridge scalars ----------------
    if ((int)blockIdx.x == nblocks_main) {
        __shared__ float sp[NCOEF * L];
        __shared__ float red[3][TPB / 32];
        for (int i = t; i < NCOEF * L; i += TPB) sp[i] = params[i];
        __syncthreads();
        float par = 0.f, fir = 0.f, sec = 0.f;
        for (int i = t; i < NCOEF * L; i += TPB) { float v = sp[i]; par += v * v; }
        for (int i = t; i < (NCOEF - 1) * L; i += TPB) { float d = sp[i + L] - sp[i]; fir += d * d; }
        for (int i = t; i < (NCOEF - 2) * L; i += TPB) {
            float d = sp[i + 2 * L] - 2.f * sp[i + L] + sp[i];
            sec += d * d;
        }
        par = warp_sum(par); fir = warp_sum(fir); sec = warp_sum(sec);
        int lane = t & 31, w = t >> 5;
        if (lane == 0) { red[0][w] = sec; red[1][w] = fir; red[2][w] = par; }
        __syncthreads();
        if (w == 0) {
            float s = (lane < TPB / 32) ? red[0][lane] : 0.f;
            float f = (lane < TPB / 32) ? red[1][lane] : 0.f;
            float p = (lane < TPB / 32) ? red[2][lane] : 0.f;
            s = warp_sum(s); f = warp_sum(f); p = warp_sum(p);
            if (lane == 0) {
                float* tail = out_all + (size_t)n_rows * (V + V * V + V);
                tail[0] = s; tail[1] = f; tail[2] = p;
            }
        }
        return;
    }

    // ---------------- main blocks: one thread per row ----------------
    __shared__ float  s_p[NCOEF * L];      // raw params stage (row-major [14][45])
    __shared__ float4 s_pw[L][11];         // shifted windows: s_pw[l][jj] = params[jj..jj+3][l]
    __shared__ float  s_x[RPB * XPAD];     // padded x tile
    __shared__ float2 s_M2[MTILE][51];     // staged M rows (50 float2 used, pad to 51)

    const int base = (int)blockIdx.x * RPB;
    const int nr = min(RPB, n_rows - base);

    for (int i = t; i < NCOEF * L; i += TPB) s_p[i] = params[i];
    for (int i = t; i < nr * V; i += TPB) {
        int r = i / V, c = i - r * V;
        s_x[r * XPAD + c] = x[(size_t)base * V + i];
    }
    __syncthreads();

    // build shifted-window table: one LDS.128 per lambda later
    for (int i = t; i < L * 11; i += TPB) {
        int l = i / 11, jj = i - l * 11;
        s_pw[l][jj] = make_float4(s_p[jj * L + l], s_p[(jj + 1) * L + l],
                                  s_p[(jj + 2) * L + l], s_p[(jj + 3) * L + l]);
    }
    __syncthreads();

    // -------- per-thread compute: 9 basis evals -> 45 lambdas -> out row --------
    float lam[L];
    if (t < nr) {
        float xr[V];
#pragma unroll
        for (int c = 0; c < V; c++) xr[c] = s_x[t * XPAD + c];

        const float INV_D = 11.0f / 10.0f;   // knot spacing d = 10/11
        const float k6 = 1.0f / 6.0f;
#pragma unroll
        for (int j = 0; j < V - 1; j++) {
            float xc = fminf(fmaxf(xr[j], -5.0f), 5.0f);
            float tt = (xc + 5.0f) * INV_D;
            float fj = fminf(floorf(tt), 10.0f);
            float u  = tt - fj;
            int   jj = (int)fj;
            float um = 1.0f - u;
            float u2 = u * u, u3 = u2 * u;
            float w0 = um * um * um * k6;
            float w1 = (3.0f * u3 - 6.0f * u2 + 4.0f) * k6;
            float w2 = (-3.0f * u3 + 3.0f * u2 + 3.0f * u + 1.0f) * k6;
            float w3 = u3 * k6;
#pragma unroll
            for (int i = j + 1; i < V; i++) {
                const int l = (i * (i - 1)) / 2 + j;
                float4 p = s_pw[l][jj];
                lam[l] = w0 * p.x + w1 * p.y + w2 * p.z + w3 * p.w;
            }
        }

        // out[n,i] = x_i + sum_{j<i} lam_{ij} x_j  -> direct global (5x float2)
        float o[V];
#pragma unroll
        for (int i = 0; i < V; i++) {
            float acc = xr[i];
#pragma unroll
            for (int j = 0; j < i; j++) acc += lam[(i * (i - 1)) / 2 + j] * xr[j];
            o[i] = acc;
        }
        float2* orow = (float2*)(out_all + (size_t)(base + t) * V);
#pragma unroll
        for (int q = 0; q < V / 2; q++) orow[q] = make_float2(o[2 * q], o[2 * q + 1]);
    }

    // -------- M: staged tiles of 32 rows, SMEM -> coalesced GMEM --------
    float2* Mb2 = (float2*)(out_all + (size_t)n_rows * V);
#pragma unroll
    for (int ph = 0; ph < RPB / MTILE; ph++) {
        const int r0 = ph * MTILE;
        const int cnt = min(MTILE, nr - r0);
        __syncthreads();   // s_M2 free from previous phase
        if (cnt <= 0) { __syncthreads(); continue; }

        if (t >= r0 && t < r0 + cnt) {
            float2* mrow = s_M2[t - r0];
            // fully unrolled: i,j,l all compile-time; no dynamic indexing
#pragma unroll
            for (int e2 = 0; e2 < 50; e2++) {
                const int e0 = 2 * e2, e1 = 2 * e2 + 1;
                const int i0 = e0 / V, j0 = e0 - i0 * V;
                const int i1 = e1 / V, j1 = e1 - i1 * V;
                float v0 = (i0 == j0) ? 1.0f : ((i0 > j0) ? lam[(i0 * (i0 - 1)) / 2 + j0] : 0.0f);
                float v1 = (i1 == j1) ? 1.0f : ((i1 > j1) ? lam[(i1 * (i1 - 1)) / 2 + j1] : 0.0f);
                mrow[e2] = make_float2(v0, v1);
            }
        }
        __syncthreads();

        // coalesced copy: cnt*50 float2, consecutive threads -> consecutive addresses
        const int nq = cnt * 50;
        for (int g = t; g < nq; g += TPB) {
            int r = g / 50, c = g - r * 50;
            Mb2[(size_t)(base + r0 + r) * 50 + c] = s_M2[r][c];
        }
    }

    // -------- log_d passthrough (coalesced float4) --------
    {
        float* ldo = out_all + (size_t)n_rows * (V + V * V) + (size_t)base * V;
        const float* ldi = log_d + (size_t)base * V;
        int nfl = nr * V;
        if ((nfl & 3) == 0) {
            const float4* s4 = (const float4*)ldi;
            float4* d4 = (float4*)ldo;
            for (int q = t; q < nfl / 4; q += TPB) d4[q] = s4[q];
        } else {
            for (int q = t; q < nfl; q += TPB) ldo[q] = ldi[q];
        }
    }
}

extern "C" void kernel_launch(void* const* d_in, const int* in_sizes, int n_in,
                              void* d_out, int out_size)
{
    const float* x      = (const float*)d_in[0];
    const float* log_d  = (const float*)d_in[1];
    const float* params = (const float*)d_in[2];
    float* out_all = (float*)d_out;

    // maximize smem carveout so 6 blocks/SM fit (deterministic, capture-safe host call)
    cudaFuncSetAttribute((const void*)decor_kernel,
                         cudaFuncAttributePreferredSharedMemoryCarveout, 100);

    int n_rows = in_sizes[0] / V;
    int main_blocks = (n_rows + RPB - 1) / RPB;
    decor_kernel<<<main_blocks + 1, TPB>>>(x, log_d, params, out_all, n_rows);
}

// round 7
// speedup vs baseline: 1.0038x; 1.0038x over previous
#include <cuda_runtime.h>

#define V      10
#define L      45
#define NCOEF  14
#define RPB    128          // rows per block
#define TPB    256          // 2 threads per row
#define MTILE  32           // rows staged per M phase (4 phases)
#define LSTR   49           // s_lam row stride (odd -> conflict-free)
#define MSTR   27           // s_M4 row stride in float4 (108 words -> conflict-free STS.128)

// dynamic smem layout (bytes): pw 7920 | M4 13824 | p 2520 | x 5632 | lam 25088 = 54984
#define SMEM_BYTES 54984

__device__ __forceinline__ float warp_sum(float v) {
#pragma unroll
    for (int o = 16; o > 0; o >>= 1) v += __shfl_down_sync(0xffffffffu, v, o);
    return v;
}

// M element for compile-time (i,j): 1 on diag, lam below, 0 above
__device__ __forceinline__ float melem(const float* lr, int i, int j) {
    return (i == j) ? 1.0f : ((i > j) ? lr[(i * (i - 1)) / 2 + j] : 0.0f);
}

__global__ __launch_bounds__(TPB, 4)
void decor_kernel(const float* __restrict__ x,
                  const float* __restrict__ log_d,
                  const float* __restrict__ params,
                  float* __restrict__ out_all,
                  int n_rows)
{
    extern __shared__ unsigned char smem_raw[];
    float4* s_pw  = (float4*)smem_raw;            // [L][11] shifted windows
    float4* s_M4  = s_pw + L * 11;                // [MTILE][MSTR]
    float*  s_p   = (float*)(s_M4 + MTILE * MSTR);// raw params [14][45]
    float*  s_x   = s_p + NCOEF * L;              // [RPB][11]
    float*  s_lam = s_x + RPB * 11;               // [RPB][LSTR]

    const int t = threadIdx.x;
    const int nblocks_main = (int)gridDim.x - 1;

    // ---------------- penalty block (last block) ----------------
    if ((int)blockIdx.x == nblocks_main) {
        float* sp  = s_p;                 // reuse dynamic smem
        float* red = s_x;                 // 3*8 floats
        for (int i = t; i < NCOEF * L; i += TPB) sp[i] = params[i];
        __syncthreads();
        float par = 0.f, fir = 0.f, sec = 0.f;
        for (int i = t; i < NCOEF * L; i += TPB) { float v = sp[i]; par += v * v; }
        for (int i = t; i < (NCOEF - 1) * L; i += TPB) { float d = sp[i + L] - sp[i]; fir += d * d; }
        for (int i = t; i < (NCOEF - 2) * L; i += TPB) {
            float d = sp[i + 2 * L] - 2.f * sp[i + L] + sp[i];
            sec += d * d;
        }
        par = warp_sum(par); fir = warp_sum(fir); sec = warp_sum(sec);
        int lane = t & 31, w = t >> 5;
        if (lane == 0) { red[0 * 8 + w] = sec; red[1 * 8 + w] = fir; red[2 * 8 + w] = par; }
        __syncthreads();
        if (w == 0) {
            float s = (lane < 8) ? red[0 * 8 + lane] : 0.f;
            float f = (lane < 8) ? red[1 * 8 + lane] : 0.f;
            float p = (lane < 8) ? red[2 * 8 + lane] : 0.f;
            s = warp_sum(s); f = warp_sum(f); p = warp_sum(p);
            if (lane == 0) {
                float* tail = out_all + (size_t)n_rows * (V + V * V + V);
                tail[0] = s; tail[1] = f; tail[2] = p;
            }
        }
        return;
    }

    // ---------------- main blocks ----------------
    const int base = (int)blockIdx.x * RPB;
    const int nr = min(RPB, n_rows - base);
    const int r = t & (RPB - 1);     // row within block
    const int h = t >> 7;            // half: 0 or 1 (warp-uniform)
    const int wid = t >> 5;          // warp id 0..7
    const int lane = t & 31;

    // log_d passthrough first (independent)
    {
        float* ldo = out_all + (size_t)n_rows * (V + V * V) + (size_t)base * V;
        const float* ldi = log_d + (size_t)base * V;
        int nfl = nr * V;
        if ((nfl & 3) == 0) {
            const float4* s4 = (const float4*)ldi;
            float4* d4 = (float4*)ldo;
            for (int q = t; q < nfl / 4; q += TPB) d4[q] = s4[q];
        } else {
            for (int q = t; q < nfl; q += TPB) ldo[q] = ldi[q];
        }
    }

    for (int i = t; i < NCOEF * L; i += TPB) s_p[i] = params[i];
    for (int i = t; i < nr * V; i += TPB) {
        int rr = i / V, c = i - rr * V;
        s_x[rr * 11 + c] = x[(size_t)base * V + i];
    }
    __syncthreads();

    // shifted windows: s_pw[l][jj] = params[jj..jj+3][l]
    for (int i = t; i < L * 11; i += TPB) {
        int l = i / 11, jj = i - l * 11;
        s_pw[i] = make_float4(s_p[jj * L + l], s_p[(jj + 1) * L + l],
                              s_p[(jj + 2) * L + l], s_p[(jj + 3) * L + l]);
    }
    __syncthreads();

    // -------- spline: 2 threads per row, split by j parity --------
    float xr[V];
    if (r < nr) {
#pragma unroll
        for (int c = 0; c < V; c++) xr[c] = s_x[r * 11 + c];

        const float INV_D = 11.0f / 10.0f;
        const float k6 = 1.0f / 6.0f;
        float* lr = s_lam + r * LSTR;

#define SPLINE_J(jc)                                                          \
        do {                                                                  \
            float xc = fminf(fmaxf(xr[jc], -5.0f), 5.0f);                     \
            float tt = (xc + 5.0f) * INV_D;                                   \
            float fj = fminf(floorf(tt), 10.0f);                              \
            float u  = tt - fj;                                               \
            int   jj = (int)fj;                                               \
            float um = 1.0f - u;                                              \
            float u2 = u * u, u3 = u2 * u;                                    \
            float w0 = um * um * um * k6;                                     \
            float w1 = (3.0f * u3 - 6.0f * u2 + 4.0f) * k6;                   \
            float w2 = (-3.0f * u3 + 3.0f * u2 + 3.0f * u + 1.0f) * k6;       \
            float w3 = u3 * k6;                                               \
            _Pragma("unroll")                                                 \
            for (int i = jc + 1; i < V; i++) {                                \
                const int l = (i * (i - 1)) / 2 + jc;                         \
                float4 p = s_pw[l * 11 + jj];                                 \
                lr[l] = w0 * p.x + w1 * p.y + w2 * p.z + w3 * p.w;            \
            }                                                                 \
        } while (0)

        if (h == 0) { SPLINE_J(0); SPLINE_J(2); SPLINE_J(4); SPLINE_J(6); SPLINE_J(8); }
        else        { SPLINE_J(1); SPLINE_J(3); SPLINE_J(5); SPLINE_J(7); }
#undef SPLINE_J
    }
    __syncthreads();

    // -------- out: split by i parity, xr reused from registers --------
    if (r < nr) {
        const float* lr = s_lam + r * LSTR;
        float* orow = out_all + (size_t)(base + r) * V;

#define OUT_I(ic)                                                             \
        do {                                                                  \
            float acc = xr[ic];                                               \
            _Pragma("unroll")                                                 \
            for (int j = 0; j < ic; j++)                                      \
                acc += lr[(ic * (ic - 1)) / 2 + j] * xr[j];                   \
            orow[ic] = acc;                                                   \
        } while (0)

        if (h == 0) { OUT_I(0); OUT_I(2); OUT_I(4); OUT_I(6); OUT_I(8); }
        else        { OUT_I(1); OUT_I(3); OUT_I(5); OUT_I(7); OUT_I(9); }
#undef OUT_I
    }

    // -------- M: 4 phases, warp-built staged tiles, contiguous copy-out --------
    float4* Mb4 = (float4*)(out_all + (size_t)n_rows * V);
#pragma unroll
    for (int ph = 0; ph < RPB / MTILE; ph++) {
        const int r0 = ph * MTILE;
        const int cnt = min(MTILE, nr - r0);
        if (ph > 0) __syncthreads();   // s_M4 free from previous copy
        if (cnt > 0) {
            if (lane < cnt) {
                const float* lr = s_lam + (r0 + lane) * LSTR;
                float4* mrow = s_M4 + lane * MSTR;
#pragma unroll
                for (int e = 0; e < 25; e++) {
                    if ((e & 7) == wid) {   // warp-uniform, e stays literal
                        float4 v;
                        v.x = melem(lr, (4 * e + 0) / V, (4 * e + 0) % V);
                        v.y = melem(lr, (4 * e + 1) / V, (4 * e + 1) % V);
                        v.z = melem(lr, (4 * e + 2) / V, (4 * e + 2) % V);
                        v.w = melem(lr, (4 * e + 3) / V, (4 * e + 3) % V);
                        mrow[e] = v;
                    }
                }
            }
            __syncthreads();
            // contiguous: gmem float4 index = (base+r0)*25 + g
            const int nq = cnt * 25;
            float4* dst = Mb4 + (size_t)(base + r0) * 25;
            for (int g = t; g < nq; g += TPB) {
                int rr = g / 25, c = g - rr * 25;
                dst[g] = s_M4[rr * MSTR + c];
            }
        } else {
            __syncthreads();
        }
    }
}

extern "C" void kernel_launch(void* const* d_in, const int* in_sizes, int n_in,
                              void* d_out, int out_size)
{
    const float* x      = (const float*)d_in[0];
    const float* log_d  = (const float*)d_in[1];
    const float* params = (const float*)d_in[2];
    float* out_all = (float*)d_out;

    cudaFuncSetAttribute((const void*)decor_kernel,
                         cudaFuncAttributeMaxDynamicSharedMemorySize, SMEM_BYTES);

    int n_rows = in_sizes[0] / V;
    int main_blocks = (n_rows + RPB - 1) / RPB;
    decor_kernel<<<main_blocks + 1, TPB, SMEM_BYTES>>>(x, log_d, params, out_all, n_rows);
}